// round 7
// baseline (speedup 1.0000x reference)
#include <cuda_runtime.h>
#include <cuda_bf16.h>
#include <cstdint>
#include <cstddef>

#define TSTEPS 64
#define BATCH  1024
#define OBSD   8
#define HID    512
#define M_ALL  (TSTEPS*BATCH)
#define NCHUNK 32            // K chunks of 16

// ---------------- scratch (__device__ globals; no allocation allowed) -------
__device__ float g_h [(size_t)M_ALL*HID];
__device__ float g_he[(size_t)M_ALL*HID];
__device__ float g_z1[(size_t)M_ALL*HID];
__device__ float g_z2[(size_t)M_ALL*HID];
__device__ float g_ka[(size_t)M_ALL*HID];
__device__ float g_gi[(size_t)M_ALL*3*HID];
__device__ float g_gh[(size_t)BATCH*3*HID];
__device__ float g_hs[(size_t)BATCH*HID];

// tf32 weights in fragment-packed chunk blocks:
// block(nblk, chunk) = 32KB = entries [ks(2)][w(8)][ntp(4)][r0(8)][c(4)] x 16B
__device__ uint32_t w1_t[512*512];
__device__ uint32_t w2_t[512*512];
__device__ uint32_t wo_t[512*512];
__device__ uint32_t wi_t[1536*512];
__device__ uint32_t wh_t[1536*512];

// ---------------- helpers ---------------------------------------------------
static __device__ __forceinline__ uint32_t smem_u32(const void* p){
    uint32_t a;
    asm("{ .reg .u64 t; cvta.to.shared.u64 t, %1; cvt.u32.u64 %0, t; }" : "=r"(a) : "l"(p));
    return a;
}
static __device__ __forceinline__ void cp16(uint32_t dst, const void* src){
    asm volatile("cp.async.cg.shared.global [%0], [%1], 16;" :: "r"(dst), "l"(src) : "memory");
}
#define CP_COMMIT() asm volatile("cp.async.commit_group;" ::: "memory")

static __device__ __forceinline__ uint32_t f2tf32(float f){
    uint32_t r;
    asm("cvt.rna.tf32.f32 %0, %1;" : "=r"(r) : "f"(f));
    return r;
}
static __device__ __forceinline__ void mma_tf32(float* d, const uint32_t* a, const uint32_t* b){
    asm volatile(
        "mma.sync.aligned.m16n8k8.row.col.f32.tf32.tf32.f32 "
        "{%0,%1,%2,%3}, {%4,%5,%6,%7}, {%8,%9}, {%0,%1,%2,%3};"
        : "+f"(d[0]), "+f"(d[1]), "+f"(d[2]), "+f"(d[3])
        : "r"(a[0]), "r"(a[1]), "r"(a[2]), "r"(a[3]), "r"(b[0]), "r"(b[1]));
}

// ---------------- weight conversion: [K,N] fp32 -> fragment-packed tf32 -----
__global__ void conv_wt(const float* __restrict__ W, int N, uint32_t* __restrict__ out)
{
    int idx = blockIdx.x * 256 + threadIdx.x;
    if (idx >= 512 * N) return;
    int k = idx / N, n = idx - k * N;
    int chunk = k >> 4, kk = k & 15;
    int ks = kk >> 3, cf = kk & 7;
    int c = cf & 3, bhalf = cf >> 2;
    int nblk = n >> 9;
    int wq = (n >> 6) & 7;
    int nn = n & 63;
    int ntp = (nn >> 4) & 3;
    int r08 = nn & 15;
    int pair = r08 >> 3, r0 = r08 & 7;
    int slot = pair*2 + bhalf;
    int e = (((ks*8 + wq)*4 + ntp)*8 + r0)*4 + c;
    out[(size_t)(nblk*32 + chunk)*8192 + e*4 + slot] = f2tf32(W[idx]);
}

// ---------------- obs -> hidden ---------------------------------------------
__global__ void obs_kernel(const float* __restrict__ xs, const float* __restrict__ W,
                           const float* __restrict__ b, const float* __restrict__ lng,
                           const float* __restrict__ lnb, float* __restrict__ out)
{
    int row  = blockIdx.x * 8 + threadIdx.y;
    int lane = threadIdx.x;
    const float* x = xs + (size_t)row * OBSD;
    float xv[OBSD];
#pragma unroll
    for (int i = 0; i < OBSD; i++) xv[i] = x[i];
    float v[16], s = 0.f, q = 0.f;
#pragma unroll
    for (int u = 0; u < 16; u++){
        int c = lane + u*32;
        float acc = b[c];
#pragma unroll
        for (int i = 0; i < OBSD; i++) acc = fmaf(xv[i], W[i*HID + c], acc);
        v[u] = acc; s += acc; q += acc*acc;
    }
#pragma unroll
    for (int off = 16; off; off >>= 1){
        s += __shfl_xor_sync(0xffffffffu, s, off);
        q += __shfl_xor_sync(0xffffffffu, q, off);
    }
    float m = s*(1.0f/HID), var = q*(1.0f/HID) - m*m;
    float inv = rsqrtf(var + 1e-5f);
#pragma unroll
    for (int u = 0; u < 16; u++){
        int c = lane + u*32;
        float val = (v[u]-m)*inv*lng[c] + lnb[c];
        out[(size_t)row*HID + c] = val >= 0.f ? val : 0.01f*val;
    }
}

// ---------------- tf32 mma GEMM: C[CTAM,512] = A[CTAM,512] @ W --------------
// 8 warps, warp tile CTAM x 64, K chunks of 16, fragment-packed smem.
#define OFF_BIAS 0
#define OFF_G    2048
#define OFF_B    4096
#define OFF_RED  6144
#define OFF_ST   10240
#define BSTG     32768

template<int MT, int EPI>
__global__ void __launch_bounds__(256) gemm_mma(
    const float* __restrict__ A,
    const uint32_t* __restrict__ Wt,
    const float* __restrict__ bias, const float* __restrict__ wlast, float tval,
    const float* __restrict__ lng, const float* __restrict__ lnb,
    float* __restrict__ C, int ldc,
    const float* __restrict__ h_in, float* __restrict__ kacc, float* __restrict__ hnext,
    float wk, float ck, int phase)
{
    constexpr int CTAM = MT*16;
    constexpr int ASTG = MT*1024;          // A frag entries: MT*2*8*4 * 16B
    constexpr int STG  = ASTG + BSTG;

    extern __shared__ char sm[];
    const int tid  = threadIdx.x;
    const int w    = tid >> 5;
    const int lane = tid & 31;
    const int r0   = lane >> 2;
    const int kq   = (lane & 3) * 2;       // epilogue col pair
    const int posk = (lane & 3) ^ ((r0 >> 1) & 3);   // A frag swizzle base
    const size_t m0 = (size_t)blockIdx.x * CTAM;
    const int n0   = blockIdx.y * 512;
    const int nblk = blockIdx.y;

    for (int i = tid; i < 512; i += 256){
        float b = bias[n0 + i];
        if (EPI == 0 && wlast != nullptr) b = fmaf(tval, wlast[i], b);
        *(float*)(sm + OFF_BIAS + i*4) = b;
        if (EPI == 0){
            *(float*)(sm + OFF_G + i*4) = lng[i];
            *(float*)(sm + OFF_B + i*4) = lnb[i];
        }
    }

    float acc[MT][8][4];
#pragma unroll
    for (int mt = 0; mt < MT; mt++)
#pragma unroll
        for (int nt = 0; nt < 8; nt++)
#pragma unroll
            for (int i = 0; i < 4; i++) acc[mt][nt][i] = 0.f;

    // producer decomposition (constant per thread)
    const int prow = tid >> 2;          // 0..63 (CTAM=64) / 0..31 active
    const int pq   = tid & 3;
    const int pks    = pq >> 1;
    const int pchalf = pq & 1;
    const int pmt   = prow >> 4;
    const int ppair = (prow >> 3) & 1;
    const int pr0   = prow & 7;
    const int pt    = (pr0 >> 1) & 3;
    const int pslotb = (pchalf*2 + ppair) * 4;
    const bool pact = (tid < CTAM*4);

    auto produce = [&](int c, int s){
        char* st = sm + OFF_ST + s*STG;
        // B: straight 16B async copies of pre-packed 32KB block
        uint32_t bsm = smem_u32(st + ASTG);
        const char* srcB = (const char*)Wt + (size_t)(nblk*32 + c)*BSTG;
#pragma unroll
        for (int i = 0; i < 8; i++){
            int idx = tid + i*256;
            cp16(bsm + idx*16, srcB + (size_t)idx*16);
        }
        // A: fp32 -> tf32 fragment scatter
        if (pact){
            float4 x = *(const float4*)(A + (m0+prow)*512 + c*16 + pq*4);
            uint32_t tv[4] = {f2tf32(x.x), f2tf32(x.y), f2tf32(x.z), f2tf32(x.w)};
#pragma unroll
            for (int j = 0; j < 4; j++){
                int pos = j ^ pks ^ pt;
                int off = (((pmt*2 + pks)*8 + pr0)*4 + pos)*16 + pslotb;
                *(uint32_t*)(st + off) = tv[j];
            }
        }
    };

    auto consume = [&](int s){
        const char* pA = sm + OFF_ST + s*STG;
        const char* pB = pA + ASTG;
#pragma unroll
        for (int ks = 0; ks < 2; ks++){
            uint4 aF[MT], bq[4];
            const int pos = posk ^ ks;
#pragma unroll
            for (int mt = 0; mt < MT; mt++)
                aF[mt] = *(const uint4*)(pA + ((mt*2 + ks)*32 + r0*4 + pos)*16);
#pragma unroll
            for (int ntp = 0; ntp < 4; ntp++)
                bq[ntp] = *(const uint4*)(pB + ((((ks*8 + w)*4 + ntp)*32) + lane)*16);
#pragma unroll
            for (int mt = 0; mt < MT; mt++)
#pragma unroll
                for (int ntp = 0; ntp < 4; ntp++){
                    uint32_t b0[2] = {bq[ntp].x, bq[ntp].y};
                    uint32_t b1[2] = {bq[ntp].z, bq[ntp].w};
                    mma_tf32(acc[mt][2*ntp],   (const uint32_t*)&aF[mt], b0);
                    mma_tf32(acc[mt][2*ntp+1], (const uint32_t*)&aF[mt], b1);
                }
        }
    };

    produce(0, 0); CP_COMMIT();
#pragma unroll 1
    for (int c = 0; c < NCHUNK; c++){
        if (c < NCHUNK-1){
            produce(c+1, (c+1)&1); CP_COMMIT();
            asm volatile("cp.async.wait_group 1;" ::: "memory");
        } else {
            asm volatile("cp.async.wait_group 0;" ::: "memory");
        }
        __syncthreads();
        consume(c & 1);
        __syncthreads();
    }

    // ---- epilogue ----
    const float* bS = (const float*)(sm + OFF_BIAS);
#pragma unroll
    for (int mt = 0; mt < MT; mt++)
#pragma unroll
        for (int nt = 0; nt < 8; nt++){
            int cw = w*64 + nt*8 + kq;
            acc[mt][nt][0] += bS[cw];   acc[mt][nt][1] += bS[cw+1];
            acc[mt][nt][2] += bS[cw];   acc[mt][nt][3] += bS[cw+1];
        }

    if (EPI == 0){
        float S[MT][2], Q[MT][2];
#pragma unroll
        for (int mt = 0; mt < MT; mt++){
            S[mt][0]=S[mt][1]=Q[mt][0]=Q[mt][1]=0.f;
#pragma unroll
            for (int nt = 0; nt < 8; nt++){
                float a0=acc[mt][nt][0], a1=acc[mt][nt][1];
                float a2=acc[mt][nt][2], a3=acc[mt][nt][3];
                S[mt][0]+=a0+a1; Q[mt][0]+=a0*a0+a1*a1;
                S[mt][1]+=a2+a3; Q[mt][1]+=a2*a2+a3*a3;
            }
        }
#pragma unroll
        for (int off = 1; off <= 2; off <<= 1)
#pragma unroll
            for (int mt = 0; mt < MT; mt++)
#pragma unroll
                for (int h = 0; h < 2; h++){
                    S[mt][h] += __shfl_xor_sync(0xffffffffu, S[mt][h], off);
                    Q[mt][h] += __shfl_xor_sync(0xffffffffu, Q[mt][h], off);
                }
        if ((lane & 3) == 0){
#pragma unroll
            for (int mt = 0; mt < MT; mt++)
#pragma unroll
                for (int h = 0; h < 2; h++){
                    int row = mt*16 + r0 + 8*h;
                    *(float2*)(sm + OFF_RED + (row*8 + w)*8) = make_float2(S[mt][h], Q[mt][h]);
                }
        }
        __syncthreads();
        const float* gS = (const float*)(sm + OFF_G);
        const float* nS = (const float*)(sm + OFF_B);
#pragma unroll
        for (int mt = 0; mt < MT; mt++)
#pragma unroll
            for (int h = 0; h < 2; h++){
                int row = mt*16 + r0 + 8*h;
                float Ss = 0.f, Qs = 0.f;
#pragma unroll
                for (int ww = 0; ww < 8; ww++){
                    float2 rr = *(const float2*)(sm + OFF_RED + (row*8 + ww)*8);
                    Ss += rr.x; Qs += rr.y;
                }
                float mu  = Ss * (1.0f/512);
                float inv = rsqrtf(Qs*(1.0f/512) - mu*mu + 1e-5f);
#pragma unroll
                for (int nt = 0; nt < 8; nt++){
                    int cw = w*64 + nt*8 + kq;
                    int ci = h*2;
                    float v0 = (acc[mt][nt][ci]   - mu)*inv*gS[cw]   + nS[cw];
                    float v1 = (acc[mt][nt][ci+1] - mu)*inv*gS[cw+1] + nS[cw+1];
                    v0 = v0 >= 0.f ? v0 : 0.01f*v0;
                    v1 = v1 >= 0.f ? v1 : 0.01f*v1;
                    *(float2*)(C + (m0+row)*(size_t)ldc + cw) = make_float2(v0, v1);
                }
            }
    } else if (EPI == 1){
#pragma unroll
        for (int mt = 0; mt < MT; mt++)
#pragma unroll
            for (int h = 0; h < 2; h++){
                int row = mt*16 + r0 + 8*h;
#pragma unroll
                for (int nt = 0; nt < 8; nt++){
                    int cw = w*64 + nt*8 + kq;
                    int ci = h*2;
                    *(float2*)(C + (m0+row)*(size_t)ldc + n0 + cw) =
                        make_float2(acc[mt][nt][ci], acc[mt][nt][ci+1]);
                }
            }
    } else {
#pragma unroll
        for (int mt = 0; mt < MT; mt++)
#pragma unroll
            for (int h = 0; h < 2; h++){
                int row = mt*16 + r0 + 8*h;
#pragma unroll
                for (int nt = 0; nt < 8; nt++){
                    int cw = w*64 + nt*8 + kq;
                    int ci = h*2;
                    size_t idx = (m0+row)*512 + cw;
                    float k0v = acc[mt][nt][ci], k1v = acc[mt][nt][ci+1];
                    float2 hv = *(const float2*)(h_in + idx);
                    if (phase < 3){
                        float2 ka = (phase > 0) ? *(const float2*)(kacc + idx)
                                                : make_float2(0.f, 0.f);
                        *(float2*)(kacc + idx) =
                            make_float2(fmaf(wk,k0v,ka.x), fmaf(wk,k1v,ka.y));
                        *(float2*)(hnext + idx) =
                            make_float2(fmaf(ck,k0v,hv.x), fmaf(ck,k1v,hv.y));
                    } else {
                        float2 ka = *(const float2*)(kacc + idx);
                        *(float2*)(hnext + idx) =
                            make_float2(fmaf(ck, ka.x + k0v, hv.x),
                                        fmaf(ck, ka.y + k1v, hv.y));
                    }
                }
            }
    }
}

// ---------------- GRU pointwise + zero --------------------------------------
__global__ void gru_pointwise(const float* __restrict__ gi, const float* __restrict__ gh,
                              const float* __restrict__ hprev, float* __restrict__ hout)
{
    int idx = blockIdx.x * blockDim.x + threadIdx.x;
    int b = idx >> 9, j = idx & 511;
    const float* gib = gi + (size_t)b*3*HID;
    const float* ghb = gh + (size_t)b*3*HID;
    float ir = gib[j],        hr = ghb[j];
    float iz = gib[HID+j],    hz = ghb[HID+j];
    float in_ = gib[2*HID+j], hn = ghb[2*HID+j];
    float r = 1.f/(1.f + expf(-(ir+hr)));
    float z = 1.f/(1.f + expf(-(iz+hz)));
    float n = tanhf(in_ + r*hn);
    hout[idx] = (1.f - z)*n + z*hprev[idx];
}

__global__ void zero_kernel(float* __restrict__ p, int n)
{
    int i = blockIdx.x * blockDim.x + threadIdx.x;
    if (i < n) p[i] = 0.f;
}

// ---------------- host driver ----------------------------------------------
#define SMEM4 (OFF_ST + 2*(4*1024 + BSTG))   // 83968
#define SMEM2 (OFF_ST + 2*(2*1024 + BSTG))   // 79872

extern "C" void kernel_launch(void* const* d_in, const int* in_sizes, int n_in,
                              void* d_out, int out_size)
{
    (void)in_sizes; (void)n_in; (void)out_size;
    const float* xs       = (const float*)d_in[0];
    const float* obs_W    = (const float*)d_in[1];
    const float* obs_b    = (const float*)d_in[2];
    const float* obs_lng  = (const float*)d_in[3];
    const float* obs_lnb  = (const float*)d_in[4];
    const float* ode_W1   = (const float*)d_in[5];   // [513, 512]
    const float* ode_b1   = (const float*)d_in[6];
    const float* ln1g     = (const float*)d_in[7];
    const float* ln1b     = (const float*)d_in[8];
    const float* ode_W2   = (const float*)d_in[9];
    const float* ode_b2   = (const float*)d_in[10];
    const float* ln2g     = (const float*)d_in[11];
    const float* ln2b     = (const float*)d_in[12];
    const float* ode_Wout = (const float*)d_in[13];
    const float* ode_bout = (const float*)d_in[14];
    const float* W_ih     = (const float*)d_in[15];  // [512, 1536]
    const float* b_ih     = (const float*)d_in[16];
    const float* W_hh     = (const float*)d_in[17];
    const float* b_hh     = (const float*)d_in[18];
    float* out = (float*)d_out;

    float *p_h, *p_he, *p_z1, *p_z2, *p_ka, *p_gi, *p_gh, *p_hs;
    cudaGetSymbolAddress((void**)&p_h,  g_h);
    cudaGetSymbolAddress((void**)&p_he, g_he);
    cudaGetSymbolAddress((void**)&p_z1, g_z1);
    cudaGetSymbolAddress((void**)&p_z2, g_z2);
    cudaGetSymbolAddress((void**)&p_ka, g_ka);
    cudaGetSymbolAddress((void**)&p_gi, g_gi);
    cudaGetSymbolAddress((void**)&p_gh, g_gh);
    cudaGetSymbolAddress((void**)&p_hs, g_hs);

    uint32_t *q1,*q2,*qo,*qi,*qh;
    cudaGetSymbolAddress((void**)&q1, w1_t);
    cudaGetSymbolAddress((void**)&q2, w2_t);
    cudaGetSymbolAddress((void**)&qo, wo_t);
    cudaGetSymbolAddress((void**)&qi, wi_t);
    cudaGetSymbolAddress((void**)&qh, wh_t);

    cudaFuncSetAttribute(gemm_mma<4,0>, cudaFuncAttributeMaxDynamicSharedMemorySize, SMEM4);
    cudaFuncSetAttribute(gemm_mma<4,1>, cudaFuncAttributeMaxDynamicSharedMemorySize, SMEM4);
    cudaFuncSetAttribute(gemm_mma<4,2>, cudaFuncAttributeMaxDynamicSharedMemorySize, SMEM4);
    cudaFuncSetAttribute(gemm_mma<2,1>, cudaFuncAttributeMaxDynamicSharedMemorySize, SMEM2);

    // 0) weight tf32 fragment-pack (tiny, once per launch)
    conv_wt<<<(512*512 +255)/256, 256>>>(ode_W1,  512,  q1);
    conv_wt<<<(512*512 +255)/256, 256>>>(ode_W2,  512,  q2);
    conv_wt<<<(512*512 +255)/256, 256>>>(ode_Wout,512,  qo);
    conv_wt<<<(512*1536+255)/256, 256>>>(W_ih,    1536, qi);
    conv_wt<<<(512*1536+255)/256, 256>>>(W_hh,    1536, qh);

    // 1) obs -> hidden
    obs_kernel<<<M_ALL/8, dim3(32,8)>>>(xs, obs_W, obs_b, obs_lng, obs_lnb, p_h);

    // 2) RK4 batched over all T*B rows
    const float dt = 0.25f;
    const float* w1last = ode_W1 + (size_t)HID*HID;   // row 512 of [513,512]
    for (int s = 0; s < 4; s++){
        float t0 = dt * (float)s;
        float te[4] = {t0, t0 + 0.5f*dt, t0 + 0.5f*dt, t0 + dt};
        float wk[4] = {1.f, 2.f, 2.f, 1.f};
        float ck[4] = {0.5f*dt, 0.5f*dt, dt, dt/6.f};
        for (int p = 0; p < 4; p++){
            const float* in = (p == 0) ? p_h : p_he;
            gemm_mma<4,0><<<dim3(M_ALL/64,1), 256, SMEM4>>>(
                in, q1, ode_b1, w1last, te[p], ln1g, ln1b,
                p_z1, HID, nullptr, nullptr, nullptr, 0.f, 0.f, 0);
            gemm_mma<4,0><<<dim3(M_ALL/64,1), 256, SMEM4>>>(
                p_z1, q2, ode_b2, nullptr, 0.f, ln2g, ln2b,
                p_z2, HID, nullptr, nullptr, nullptr, 0.f, 0.f, 0);
            gemm_mma<4,2><<<dim3(M_ALL/64,1), 256, SMEM4>>>(
                p_z2, qo, ode_bout, nullptr, 0.f, nullptr, nullptr,
                nullptr, 0, p_h, p_ka, (p == 3) ? p_h : p_he, wk[p], ck[p], p);
        }
    }

    // 3) GRU input gates for all timesteps
    gemm_mma<4,1><<<dim3(M_ALL/64,3), 256, SMEM4>>>(
        p_h, qi, b_ih, nullptr, 0.f, nullptr, nullptr,
        p_gi, 3*HID, nullptr, nullptr, nullptr, 0.f, 0.f, 0);

    // 4) Sequential GRU
    zero_kernel<<<(BATCH*HID + 255)/256, 256>>>(p_hs, BATCH*HID);
    for (int t = 0; t < TSTEPS; t++){
        gemm_mma<2,1><<<dim3(BATCH/32,3), 256, SMEM2>>>(
            p_hs, qh, b_hh, nullptr, 0.f, nullptr, nullptr,
            p_gh, 3*HID, nullptr, nullptr, nullptr, 0.f, 0.f, 0);
        gru_pointwise<<<(BATCH*HID)/512, 512>>>(
            p_gi + (size_t)t*BATCH*3*HID, p_gh, p_hs,
            (t == TSTEPS-1) ? out : p_hs);
    }
}